// round 15
// baseline (speedup 1.0000x reference)
#include <cuda_runtime.h>

#define BSZ   8
#define NN    20000
#define FIN   256
#define NH    8
#define ND    64
#define EE    160000

#define RPB   544        // rows per block (multiple of 32)
#define NBX   37         // ceil(20000/544)

typedef unsigned long long ull;

// Scratch (device globals — no allocation allowed)
__device__ float g_u[BSZ * 2 * NH * FIN];          // [b][o][f], o = s*8+h
__device__ float g_scores[2][BSZ * NN * NH];       // [s][(b*N+n)*8+h]
__device__ int   g_idx_is64;

__device__ __forceinline__ void fma2(ull& d, ull a, ull b) {
    asm("fma.rn.f32x2 %0, %1, %2, %0;" : "+l"(d) : "l"(a), "l"(b));
}
__device__ __forceinline__ void upk2(ull v, float& lo, float& hi) {
    asm("mov.b64 {%0, %1}, %2;" : "=f"(lo), "=f"(hi) : "l"(v));
}

// ---------------------------------------------------------------------------
// K1: u[b][o][f] = sum_d W[h*64+d][f] * scoring_{s}[b][h][d]  (R14 version)
// ---------------------------------------------------------------------------
__global__ void __launch_bounds__(256)
k_prep(const float* __restrict__ W,
       const float* __restrict__ src,
       const float* __restrict__ trg,
       const unsigned int* __restrict__ head_words) {
    if (blockIdx.x == 0 && threadIdx.x < 32) {
        unsigned int nz = 0;
        for (int i = threadIdx.x; i < 512; i += 32)
            nz |= head_words[2 * i + 1];
        nz = __reduce_or_sync(0xffffffffu, nz);
        if (threadIdx.x == 0) g_idx_is64 = (nz == 0u) ? 1 : 0;
    }

    const int blk = blockIdx.x;
    const int fq  = blk & 3;
    const int grp = blk >> 2;
    const int h   = grp & 7;
    const int s   = (grp >> 3) & 1;
    const int b   = grp >> 4;
    const int t   = threadIdx.x;

    __shared__ float  sc[ND];
    __shared__ float4 Wt4[1024];

    const float* scp = (s == 0 ? src : trg) + (b * NH + h) * ND;
    if (t < ND) sc[t] = scp[t];

    const float4* Wb = (const float4*)W;
#pragma unroll
    for (int k = 0; k < 4; k++) {
        int e = t + k * 256;
        int d = e >> 4, j = e & 15;
        Wt4[e] = Wb[(size_t)(h * ND + d) * 64 + fq * 16 + j];
    }
    __syncthreads();

    if (t < 64) {
        const float* Ws = (const float*)Wt4;
        float a0 = 0.f, a1 = 0.f, a2 = 0.f, a3 = 0.f;
#pragma unroll
        for (int d = 0; d < ND; d += 4) {
            a0 = fmaf(Ws[(d + 0) * 64 + t], sc[d + 0], a0);
            a1 = fmaf(Ws[(d + 1) * 64 + t], sc[d + 1], a1);
            a2 = fmaf(Ws[(d + 2) * 64 + t], sc[d + 2], a2);
            a3 = fmaf(Ws[(d + 3) * 64 + t], sc[d + 3], a3);
        }
        g_u[grp * FIN + fq * 64 + t] = (a0 + a1) + (a2 + a3);
    }
}

// ---------------------------------------------------------------------------
// K2: scores[(b,n,o)] = sum_f ch[b][n][f] * u[b][o][f]
//
// Lane map: og = lane>>3 (4 outs), fc = lane&7 (16B chunk of 128B line).
// One c-LDG = ONE fully-consumed 128B line (8 wf/row vs R3's 64).
// Warp-iter: 4 rows x 16 outs; acc[4][4] packed f32x2 = 32 regs.
// u in smem, linear layout: LDS phase-octet = fc 0..7 -> conflict-free.
// Double-buffered c prefetch + fully unrolled fi loop -> load-to-use >= 1
// iteration (R6's fatal zero-distance stall fixed).
// Reduce over fc lanes (3 shfl_xor); lanes fc==0 store float4.
// ---------------------------------------------------------------------------
__global__ void __launch_bounds__(256, 2)
k_scores(const float* __restrict__ ch) {
    __shared__ float4 u_s[1024];        // u[b] linear: chunk = o*64 + fi*8 + fc
    const int b = blockIdx.y;

    for (int e = threadIdx.x; e < 1024; e += 256)
        u_s[e] = ((const float4*)(g_u + b * 4096))[e];
    __syncthreads();

    const int w    = threadIdx.x >> 5;
    const int lane = threadIdx.x & 31;
    const int og   = lane >> 3;
    const int fc   = lane & 7;
    const int s_tab = og >> 1;
    const int hoff  = (og & 1) * 4;

    const ulonglong2* us = (const ulonglong2*)u_s;
    const int ub = og * 4 * 64 + fc;    // + k*64 + fi*8

    const float* chb = ch + (size_t)b * NN * FIN;
    const int r0   = blockIdx.x * RPB;
    const int rend = (r0 + RPB < NN) ? r0 + RPB : NN;

    for (int rb = r0 + w * 4; rb < rend; rb += 32) {
        const ulonglong2* pr[4];
#pragma unroll
        for (int r = 0; r < 4; r++) {
            int rc = rb + r;
            if (rc >= NN) rc = NN - 1;
            pr[r] = (const ulonglong2*)(chb + (size_t)rc * FIN) + fc;
        }

        ull acc[4][4];
#pragma unroll
        for (int r = 0; r < 4; r++)
#pragma unroll
            for (int k = 0; k < 4; k++) acc[r][k] = 0ull;

        // Prefetch fi = 0.
        ulonglong2 cur[4];
#pragma unroll
        for (int r = 0; r < 4; r++) cur[r] = pr[r][0];

#pragma unroll
        for (int fi = 0; fi < 8; fi++) {
            ulonglong2 nxt[4];
            if (fi < 7) {
#pragma unroll
                for (int r = 0; r < 4; r++) nxt[r] = pr[r][(fi + 1) * 8];
            }
            const int fs = fi * 8;
            ulonglong2 u0 = us[ub + 0 * 64 + fs];
            ulonglong2 u1 = us[ub + 1 * 64 + fs];
            ulonglong2 u2 = us[ub + 2 * 64 + fs];
            ulonglong2 u3 = us[ub + 3 * 64 + fs];

#pragma unroll
            for (int r = 0; r < 4; r++) {
                fma2(acc[r][0], cur[r].x, u0.x); fma2(acc[r][0], cur[r].y, u0.y);
                fma2(acc[r][1], cur[r].x, u1.x); fma2(acc[r][1], cur[r].y, u1.y);
                fma2(acc[r][2], cur[r].x, u2.x); fma2(acc[r][2], cur[r].y, u2.y);
                fma2(acc[r][3], cur[r].x, u3.x); fma2(acc[r][3], cur[r].y, u3.y);
            }
            if (fi < 7) {
#pragma unroll
                for (int r = 0; r < 4; r++) cur[r] = nxt[r];
            }
        }

        // Epilogue: packed halves add, reduce across fc lanes, store float4.
#pragma unroll
        for (int r = 0; r < 4; r++) {
            float v[4];
#pragma unroll
            for (int k = 0; k < 4; k++) {
                float lo, hi; upk2(acc[r][k], lo, hi);
                v[k] = lo + hi;
            }
#pragma unroll
            for (int k = 0; k < 4; k++) {
                v[k] += __shfl_xor_sync(0xffffffffu, v[k], 1);
                v[k] += __shfl_xor_sync(0xffffffffu, v[k], 2);
                v[k] += __shfl_xor_sync(0xffffffffu, v[k], 4);
            }
            if (fc == 0 && rb + r < NN) {
                float4 o4 = make_float4(v[0], v[1], v[2], v[3]);
                *(float4*)&g_scores[s_tab][((size_t)b * NN + rb + r) * NH + hoff] = o4;
            }
        }
    }
}

// ---------------------------------------------------------------------------
// K3: out[i] = sigmoid(scores_src[head[i]] + scores_trg[tail[i]])
// ---------------------------------------------------------------------------
__global__ void k_gather(const void* __restrict__ head,
                         const void* __restrict__ tail,
                         float* __restrict__ out, int total) {
    int i = blockIdx.x * blockDim.x + threadIdx.x;
    if (i * 4 >= total) return;

    long long h[4], t[4];
    if (g_idx_is64) {
        longlong2 a0 = ((const longlong2*)head)[2 * i];
        longlong2 a1 = ((const longlong2*)head)[2 * i + 1];
        longlong2 b0 = ((const longlong2*)tail)[2 * i];
        longlong2 b1 = ((const longlong2*)tail)[2 * i + 1];
        h[0] = a0.x; h[1] = a0.y; h[2] = a1.x; h[3] = a1.y;
        t[0] = b0.x; t[1] = b0.y; t[2] = b1.x; t[3] = b1.y;
    } else {
        int4 a = ((const int4*)head)[i];
        int4 c = ((const int4*)tail)[i];
        h[0] = a.x; h[1] = a.y; h[2] = a.z; h[3] = a.w;
        t[0] = c.x; t[1] = c.y; t[2] = c.z; t[3] = c.w;
    }

    float x[4];
#pragma unroll
    for (int k = 0; k < 4; k++)
        x[k] = g_scores[0][h[k]] + g_scores[1][t[k]];

    float4 r;
    r.x = 1.f / (1.f + __expf(-x[0]));
    r.y = 1.f / (1.f + __expf(-x[1]));
    r.z = 1.f / (1.f + __expf(-x[2]));
    r.w = 1.f / (1.f + __expf(-x[3]));
    ((float4*)out)[i] = r;
}

// ---------------------------------------------------------------------------
extern "C" void kernel_launch(void* const* d_in, const int* in_sizes, int n_in,
                              void* d_out, int out_size) {
    const float* ch   = (const float*)d_in[0];
    const void*  head = d_in[1];
    const void*  tail = d_in[2];
    const float* W    = (const float*)d_in[3];
    const float* src  = (const float*)d_in[4];
    const float* trg  = (const float*)d_in[5];
    float* out = (float*)d_out;

    k_prep<<<BSZ * 2 * NH * 4, 256>>>(W, src, trg, (const unsigned int*)head);

    dim3 g2(NBX, BSZ);
    k_scores<<<g2, 256>>>(ch);

    int total = BSZ * EE;                       // 1,280,000 (multiple of 4)
    int groups = total / 4;
    k_gather<<<(groups + 255) / 256, 256>>>(head, tail, out, total);
}

// round 16
// speedup vs baseline: 2.1076x; 2.1076x over previous
#include <cuda_runtime.h>

#define BSZ   8
#define NN    20000
#define FIN   256
#define NH    8
#define ND    64
#define EE    160000

#define RPB   544        // rows per block (multiple of 128)
#define NBX   37         // ceil(20000/544)

typedef unsigned long long ull;

// Scratch (device globals — no allocation allowed)
__device__ float g_u[BSZ * 2 * NH * FIN];          // [b][s][h][f]  (o = s*8+h)
__device__ float g_scores[2][BSZ * NN * NH];       // [s][(b*N+n)*8+h]
__device__ int   g_idx_is64;

__device__ __forceinline__ void fma2(ull& d, ull a, ull b) {
    asm("fma.rn.f32x2 %0, %1, %2, %0;" : "+l"(d) : "l"(a), "l"(b));
}
__device__ __forceinline__ void upk2(ull v, float& lo, float& hi) {
    asm("mov.b64 {%0, %1}, %2;" : "=f"(lo), "=f"(hi) : "l"(v));
}
// Streaming (evict-first) 16B load: ch is read exactly once.
__device__ __forceinline__ ulonglong2 ldcs2(const ulonglong2* p) {
    ulonglong2 v;
    asm("ld.global.cs.v2.u64 {%0, %1}, [%2];"
        : "=l"(v.x), "=l"(v.y) : "l"(p));
    return v;
}

// ---------------------------------------------------------------------------
// K1: u[b][o][f] = sum_d W[h*64+d][f] * scoring_{s}[b][h][d]  (R14 version)
// One block per (b,s,h) x f-quarter; 16KB W quarter staged in one shot.
// Block 0 warp 0 additionally sniffs index dtype (int64 -> odd words all 0).
// ---------------------------------------------------------------------------
__global__ void __launch_bounds__(256)
k_prep(const float* __restrict__ W,
       const float* __restrict__ src,
       const float* __restrict__ trg,
       const unsigned int* __restrict__ head_words) {
    if (blockIdx.x == 0 && threadIdx.x < 32) {
        unsigned int nz = 0;
        for (int i = threadIdx.x; i < 512; i += 32)
            nz |= head_words[2 * i + 1];
        nz = __reduce_or_sync(0xffffffffu, nz);
        if (threadIdx.x == 0) g_idx_is64 = (nz == 0u) ? 1 : 0;
    }

    const int blk = blockIdx.x;
    const int fq  = blk & 3;
    const int grp = blk >> 2;
    const int h   = grp & 7;
    const int s   = (grp >> 3) & 1;
    const int b   = grp >> 4;
    const int t   = threadIdx.x;

    __shared__ float  sc[ND];
    __shared__ float4 Wt4[1024];

    const float* scp = (s == 0 ? src : trg) + (b * NH + h) * ND;
    if (t < ND) sc[t] = scp[t];

    const float4* Wb = (const float4*)W;
#pragma unroll
    for (int k = 0; k < 4; k++) {
        int e = t + k * 256;
        int d = e >> 4, j = e & 15;
        Wt4[e] = Wb[(size_t)(h * ND + d) * 64 + fq * 16 + j];
    }
    __syncthreads();

    if (t < 64) {
        const float* Ws = (const float*)Wt4;
        float a0 = 0.f, a1 = 0.f, a2 = 0.f, a3 = 0.f;
#pragma unroll
        for (int d = 0; d < ND; d += 4) {
            a0 = fmaf(Ws[(d + 0) * 64 + t], sc[d + 0], a0);
            a1 = fmaf(Ws[(d + 1) * 64 + t], sc[d + 1], a1);
            a2 = fmaf(Ws[(d + 2) * 64 + t], sc[d + 2], a2);
            a3 = fmaf(Ws[(d + 3) * 64 + t], sc[d + 3], a3);
        }
        g_u[grp * FIN + fq * 64 + t] = (a0 + a1) + (a2 + a3);
    }
}

// ---------------------------------------------------------------------------
// K2: scores[(b,n,o)] = sum_f ch[b][n][f] * u[b][o][f]
// (R3 structure verbatim — best measured; only change: c loads use ld.cs)
// ---------------------------------------------------------------------------
__global__ void __launch_bounds__(256, 2)
k_scores(const float* __restrict__ ch) {
    __shared__ float4 u_s[16 * 64];
    const int b = blockIdx.y;

    // Load u[b] once per block, swizzled: idx = o*64 + fq*32 + (fi4 ^ (o>>2) ^ (fq<<2))
    for (int e = threadIdx.x; e < 1024; e += 256) {
        int o = e >> 6, f4 = e & 63;
        int fqf = f4 >> 5, fi4 = f4 & 31;
        float4 v = *(const float4*)(g_u + ((b * 16 + o) << 8) + (f4 << 2));
        u_s[(o << 6) + (fqf << 5) + (fi4 ^ (o >> 2) ^ (fqf << 2))] = v;
    }
    __syncthreads();

    const int w    = threadIdx.x >> 5;
    const int lane = threadIdx.x & 31;
    const int og   = lane & 3;
    const int rl   = (lane >> 2) & 3;
    const int fq   = lane >> 4;

    const int r0   = blockIdx.x * RPB;
    const int rend = (r0 + RPB < NN) ? r0 + RPB : NN;

    const float* chb = ch + (size_t)b * NN * FIN + fq * 128;
    const ulonglong2* us = (const ulonglong2*)u_s;

    const int mask = og ^ (fq << 2);
    int ub0 = (og * 4 + 0) * 64 + fq * 32;
    int ub1 = (og * 4 + 1) * 64 + fq * 32;
    int ub2 = (og * 4 + 2) * 64 + fq * 32;
    int ub3 = (og * 4 + 3) * 64 + fq * 32;

    for (int rowbase = r0 + w * 16; rowbase < rend; rowbase += 128) {
        int row0 = rowbase + 0 * 4 + rl;
        int row1 = rowbase + 1 * 4 + rl;
        int row2 = rowbase + 2 * 4 + rl;
        int row3 = rowbase + 3 * 4 + rl;
        const ulonglong2* p0 = (const ulonglong2*)(chb + (size_t)(row0 < NN ? row0 : NN - 1) * FIN);
        const ulonglong2* p1 = (const ulonglong2*)(chb + (size_t)(row1 < NN ? row1 : NN - 1) * FIN);
        const ulonglong2* p2 = (const ulonglong2*)(chb + (size_t)(row2 < NN ? row2 : NN - 1) * FIN);
        const ulonglong2* p3 = (const ulonglong2*)(chb + (size_t)(row3 < NN ? row3 : NN - 1) * FIN);

        ull acc[4][4];
#pragma unroll
        for (int j = 0; j < 4; j++)
#pragma unroll
            for (int i = 0; i < 4; i++) acc[j][i] = 0ull;

#pragma unroll 8
        for (int fi4 = 0; fi4 < 32; fi4++) {
            ulonglong2 c0 = ldcs2(p0 + fi4);
            ulonglong2 c1 = ldcs2(p1 + fi4);
            ulonglong2 c2 = ldcs2(p2 + fi4);
            ulonglong2 c3 = ldcs2(p3 + fi4);
            int sx = fi4 ^ mask;
            ulonglong2 u0 = us[ub0 + sx];
            ulonglong2 u1 = us[ub1 + sx];
            ulonglong2 u2 = us[ub2 + sx];
            ulonglong2 u3 = us[ub3 + sx];

            fma2(acc[0][0], c0.x, u0.x); fma2(acc[0][0], c0.y, u0.y);
            fma2(acc[0][1], c0.x, u1.x); fma2(acc[0][1], c0.y, u1.y);
            fma2(acc[0][2], c0.x, u2.x); fma2(acc[0][2], c0.y, u2.y);
            fma2(acc[0][3], c0.x, u3.x); fma2(acc[0][3], c0.y, u3.y);

            fma2(acc[1][0], c1.x, u0.x); fma2(acc[1][0], c1.y, u0.y);
            fma2(acc[1][1], c1.x, u1.x); fma2(acc[1][1], c1.y, u1.y);
            fma2(acc[1][2], c1.x, u2.x); fma2(acc[1][2], c1.y, u2.y);
            fma2(acc[1][3], c1.x, u3.x); fma2(acc[1][3], c1.y, u3.y);

            fma2(acc[2][0], c2.x, u0.x); fma2(acc[2][0], c2.y, u0.y);
            fma2(acc[2][1], c2.x, u1.x); fma2(acc[2][1], c2.y, u1.y);
            fma2(acc[2][2], c2.x, u2.x); fma2(acc[2][2], c2.y, u2.y);
            fma2(acc[2][3], c2.x, u3.x); fma2(acc[2][3], c2.y, u3.y);

            fma2(acc[3][0], c3.x, u0.x); fma2(acc[3][0], c3.y, u0.y);
            fma2(acc[3][1], c3.x, u1.x); fma2(acc[3][1], c3.y, u1.y);
            fma2(acc[3][2], c3.x, u2.x); fma2(acc[3][2], c3.y, u2.y);
            fma2(acc[3][3], c3.x, u3.x); fma2(acc[3][3], c3.y, u3.y);
        }

        const int s_tab = og >> 1;
        const int hoff  = (og & 1) * 4;
        int rows[4] = {row0, row1, row2, row3};
#pragma unroll
        for (int j = 0; j < 4; j++) {
            float v[4];
#pragma unroll
            for (int i = 0; i < 4; i++) {
                float lo, hi; upk2(acc[j][i], lo, hi);
                v[i] = lo + hi;
            }
#pragma unroll
            for (int i = 0; i < 4; i++)
                v[i] += __shfl_xor_sync(0xffffffffu, v[i], 16);
            if (fq == 0 && rows[j] < NN) {
                float4 o4 = make_float4(v[0], v[1], v[2], v[3]);
                *(float4*)&g_scores[s_tab][((size_t)b * NN + rows[j]) * NH + hoff] = o4;
            }
        }
    }
}

// ---------------------------------------------------------------------------
// K3: out[i] = sigmoid(scores_src[head[i]] + scores_trg[tail[i]])
// 4 edges per thread (best measured variant).
// ---------------------------------------------------------------------------
__global__ void k_gather(const void* __restrict__ head,
                         const void* __restrict__ tail,
                         float* __restrict__ out, int total) {
    int i = blockIdx.x * blockDim.x + threadIdx.x;   // edge group of 4
    if (i * 4 >= total) return;

    long long h[4], t[4];
    if (g_idx_is64) {
        longlong2 a0 = ((const longlong2*)head)[2 * i];
        longlong2 a1 = ((const longlong2*)head)[2 * i + 1];
        longlong2 b0 = ((const longlong2*)tail)[2 * i];
        longlong2 b1 = ((const longlong2*)tail)[2 * i + 1];
        h[0] = a0.x; h[1] = a0.y; h[2] = a1.x; h[3] = a1.y;
        t[0] = b0.x; t[1] = b0.y; t[2] = b1.x; t[3] = b1.y;
    } else {
        int4 a = ((const int4*)head)[i];
        int4 c = ((const int4*)tail)[i];
        h[0] = a.x; h[1] = a.y; h[2] = a.z; h[3] = a.w;
        t[0] = c.x; t[1] = c.y; t[2] = c.z; t[3] = c.w;
    }

    float x[4];
#pragma unroll
    for (int k = 0; k < 4; k++)
        x[k] = g_scores[0][h[k]] + g_scores[1][t[k]];

    float4 r;
    r.x = 1.f / (1.f + __expf(-x[0]));
    r.y = 1.f / (1.f + __expf(-x[1]));
    r.z = 1.f / (1.f + __expf(-x[2]));
    r.w = 1.f / (1.f + __expf(-x[3]));
    ((float4*)out)[i] = r;
}

// ---------------------------------------------------------------------------
extern "C" void kernel_launch(void* const* d_in, const int* in_sizes, int n_in,
                              void* d_out, int out_size) {
    const float* ch   = (const float*)d_in[0];
    const void*  head = d_in[1];
    const void*  tail = d_in[2];
    const float* W    = (const float*)d_in[3];
    const float* src  = (const float*)d_in[4];
    const float* trg  = (const float*)d_in[5];
    float* out = (float*)d_out;

    k_prep<<<BSZ * 2 * NH * 4, 256>>>(W, src, trg, (const unsigned int*)head);

    dim3 g2(NBX, BSZ);
    k_scores<<<g2, 256>>>(ch);

    int total = BSZ * EE;                       // 1,280,000 (multiple of 4)
    int groups = total / 4;
    k_gather<<<(groups + 255) / 256, 256>>>(head, tail, out, total);
}

// round 17
// speedup vs baseline: 2.4215x; 1.1489x over previous
#include <cuda_runtime.h>

#define BSZ   8
#define NN    20000
#define FIN   256
#define NH    8
#define ND    64
#define EE    160000

#define RPB   544        // rows per block (multiple of 128)
#define NBX   37         // ceil(20000/544)

typedef unsigned long long ull;

// Scratch (device globals — no allocation allowed)
__device__ float g_u[BSZ * 2 * NH * FIN];          // [b][s][h][f]  (o = s*8+h)
__device__ float g_scores[2][BSZ * NN * NH];       // [s][(b*N+n)*8+h]
__device__ int   g_idx_is64;

__device__ __forceinline__ void fma2(ull& d, ull a, ull b) {
    asm("fma.rn.f32x2 %0, %1, %2, %0;" : "+l"(d) : "l"(a), "l"(b));
}
__device__ __forceinline__ void upk2(ull v, float& lo, float& hi) {
    asm("mov.b64 {%0, %1}, %2;" : "=f"(lo), "=f"(hi) : "l"(v));
}
// 256-bit streaming load (sm_100+): one LDG.E.256 replaces two LDG.E.128 ->
// halves c-LDG instruction count and L1 wavefronts. Evict-first (.cs): ch is
// read exactly once. Results packed to f32x2 operands for fma.rn.f32x2.
__device__ __forceinline__ void ldcs8(const void* p, ull& q0, ull& q1,
                                      ull& q2, ull& q3) {
    float a0, a1, a2, a3, a4, a5, a6, a7;
    asm("ld.global.cs.v8.f32 {%0,%1,%2,%3,%4,%5,%6,%7}, [%8];"
        : "=f"(a0), "=f"(a1), "=f"(a2), "=f"(a3),
          "=f"(a4), "=f"(a5), "=f"(a6), "=f"(a7)
        : "l"(p));
    asm("mov.b64 %0, {%1,%2};" : "=l"(q0) : "f"(a0), "f"(a1));
    asm("mov.b64 %0, {%1,%2};" : "=l"(q1) : "f"(a2), "f"(a3));
    asm("mov.b64 %0, {%1,%2};" : "=l"(q2) : "f"(a4), "f"(a5));
    asm("mov.b64 %0, {%1,%2};" : "=l"(q3) : "f"(a6), "f"(a7));
}

// ---------------------------------------------------------------------------
// K1: u[b][o][f] = sum_d W[h*64+d][f] * scoring_{s}[b][h][d]  (R14 version)
// ---------------------------------------------------------------------------
__global__ void __launch_bounds__(256)
k_prep(const float* __restrict__ W,
       const float* __restrict__ src,
       const float* __restrict__ trg,
       const unsigned int* __restrict__ head_words) {
    if (blockIdx.x == 0 && threadIdx.x < 32) {
        unsigned int nz = 0;
        for (int i = threadIdx.x; i < 512; i += 32)
            nz |= head_words[2 * i + 1];
        nz = __reduce_or_sync(0xffffffffu, nz);
        if (threadIdx.x == 0) g_idx_is64 = (nz == 0u) ? 1 : 0;
    }

    const int blk = blockIdx.x;
    const int fq  = blk & 3;
    const int grp = blk >> 2;
    const int h   = grp & 7;
    const int s   = (grp >> 3) & 1;
    const int b   = grp >> 4;
    const int t   = threadIdx.x;

    __shared__ float  sc[ND];
    __shared__ float4 Wt4[1024];

    const float* scp = (s == 0 ? src : trg) + (b * NH + h) * ND;
    if (t < ND) sc[t] = scp[t];

    const float4* Wb = (const float4*)W;
#pragma unroll
    for (int k = 0; k < 4; k++) {
        int e = t + k * 256;
        int d = e >> 4, j = e & 15;
        Wt4[e] = Wb[(size_t)(h * ND + d) * 64 + fq * 16 + j];
    }
    __syncthreads();

    if (t < 64) {
        const float* Ws = (const float*)Wt4;
        float a0 = 0.f, a1 = 0.f, a2 = 0.f, a3 = 0.f;
#pragma unroll
        for (int d = 0; d < ND; d += 4) {
            a0 = fmaf(Ws[(d + 0) * 64 + t], sc[d + 0], a0);
            a1 = fmaf(Ws[(d + 1) * 64 + t], sc[d + 1], a1);
            a2 = fmaf(Ws[(d + 2) * 64 + t], sc[d + 2], a2);
            a3 = fmaf(Ws[(d + 3) * 64 + t], sc[d + 3], a3);
        }
        g_u[grp * FIN + fq * 64 + t] = (a0 + a1) + (a2 + a3);
    }
}

// ---------------------------------------------------------------------------
// K2: scores[(b,n,o)] = sum_f ch[b][n][f] * u[b][o][f]
// R3/R16 structure; only change: c loaded with 256-bit ld.cs (fi steps 2
// chunks per iteration -> half the LDG instructions, half the wavefronts).
// ---------------------------------------------------------------------------
__global__ void __launch_bounds__(256, 2)
k_scores(const float* __restrict__ ch) {
    __shared__ float4 u_s[16 * 64];
    const int b = blockIdx.y;

    // Load u[b] once per block, swizzled: idx = o*64 + fq*32 + (fi4 ^ (o>>2) ^ (fq<<2))
    for (int e = threadIdx.x; e < 1024; e += 256) {
        int o = e >> 6, f4 = e & 63;
        int fqf = f4 >> 5, fi4 = f4 & 31;
        float4 v = *(const float4*)(g_u + ((b * 16 + o) << 8) + (f4 << 2));
        u_s[(o << 6) + (fqf << 5) + (fi4 ^ (o >> 2) ^ (fqf << 2))] = v;
    }
    __syncthreads();

    const int w    = threadIdx.x >> 5;
    const int lane = threadIdx.x & 31;
    const int og   = lane & 3;
    const int rl   = (lane >> 2) & 3;
    const int fq   = lane >> 4;

    const int r0   = blockIdx.x * RPB;
    const int rend = (r0 + RPB < NN) ? r0 + RPB : NN;

    const float* chb = ch + (size_t)b * NN * FIN + fq * 128;
    const ulonglong2* us = (const ulonglong2*)u_s;

    const int mask = og ^ (fq << 2);
    int ub0 = (og * 4 + 0) * 64 + fq * 32;
    int ub1 = (og * 4 + 1) * 64 + fq * 32;
    int ub2 = (og * 4 + 2) * 64 + fq * 32;
    int ub3 = (og * 4 + 3) * 64 + fq * 32;

    for (int rowbase = r0 + w * 16; rowbase < rend; rowbase += 128) {
        int row0 = rowbase + 0 * 4 + rl;
        int row1 = rowbase + 1 * 4 + rl;
        int row2 = rowbase + 2 * 4 + rl;
        int row3 = rowbase + 3 * 4 + rl;
        const char* p0 = (const char*)(chb + (size_t)(row0 < NN ? row0 : NN - 1) * FIN);
        const char* p1 = (const char*)(chb + (size_t)(row1 < NN ? row1 : NN - 1) * FIN);
        const char* p2 = (const char*)(chb + (size_t)(row2 < NN ? row2 : NN - 1) * FIN);
        const char* p3 = (const char*)(chb + (size_t)(row3 < NN ? row3 : NN - 1) * FIN);

        ull acc[4][4];
#pragma unroll
        for (int j = 0; j < 4; j++)
#pragma unroll
            for (int i = 0; i < 4; i++) acc[j][i] = 0ull;

#pragma unroll 4
        for (int fi8 = 0; fi8 < 16; fi8++) {
            // One 32B load per row covers chunks fi4 = 2*fi8 and 2*fi8+1.
            ull c0a, c0b, c0c, c0d;  ldcs8(p0 + fi8 * 32, c0a, c0b, c0c, c0d);
            ull c1a, c1b, c1c, c1d;  ldcs8(p1 + fi8 * 32, c1a, c1b, c1c, c1d);
            ull c2a, c2b, c2c, c2d;  ldcs8(p2 + fi8 * 32, c2a, c2b, c2c, c2d);
            ull c3a, c3b, c3c, c3d;  ldcs8(p3 + fi8 * 32, c3a, c3b, c3c, c3d);

            int sx0 = (2 * fi8)     ^ mask;
            int sx1 = (2 * fi8 + 1) ^ mask;
            ulonglong2 u00 = us[ub0 + sx0], u01 = us[ub0 + sx1];
            ulonglong2 u10 = us[ub1 + sx0], u11 = us[ub1 + sx1];
            ulonglong2 u20 = us[ub2 + sx0], u21 = us[ub2 + sx1];
            ulonglong2 u30 = us[ub3 + sx0], u31 = us[ub3 + sx1];

            fma2(acc[0][0], c0a, u00.x); fma2(acc[0][0], c0b, u00.y);
            fma2(acc[0][0], c0c, u01.x); fma2(acc[0][0], c0d, u01.y);
            fma2(acc[0][1], c0a, u10.x); fma2(acc[0][1], c0b, u10.y);
            fma2(acc[0][1], c0c, u11.x); fma2(acc[0][1], c0d, u11.y);
            fma2(acc[0][2], c0a, u20.x); fma2(acc[0][2], c0b, u20.y);
            fma2(acc[0][2], c0c, u21.x); fma2(acc[0][2], c0d, u21.y);
            fma2(acc[0][3], c0a, u30.x); fma2(acc[0][3], c0b, u30.y);
            fma2(acc[0][3], c0c, u31.x); fma2(acc[0][3], c0d, u31.y);

            fma2(acc[1][0], c1a, u00.x); fma2(acc[1][0], c1b, u00.y);
            fma2(acc[1][0], c1c, u01.x); fma2(acc[1][0], c1d, u01.y);
            fma2(acc[1][1], c1a, u10.x); fma2(acc[1][1], c1b, u10.y);
            fma2(acc[1][1], c1c, u11.x); fma2(acc[1][1], c1d, u11.y);
            fma2(acc[1][2], c1a, u20.x); fma2(acc[1][2], c1b, u20.y);
            fma2(acc[1][2], c1c, u21.x); fma2(acc[1][2], c1d, u21.y);
            fma2(acc[1][3], c1a, u30.x); fma2(acc[1][3], c1b, u30.y);
            fma2(acc[1][3], c1c, u31.x); fma2(acc[1][3], c1d, u31.y);

            fma2(acc[2][0], c2a, u00.x); fma2(acc[2][0], c2b, u00.y);
            fma2(acc[2][0], c2c, u01.x); fma2(acc[2][0], c2d, u01.y);
            fma2(acc[2][1], c2a, u10.x); fma2(acc[2][1], c2b, u10.y);
            fma2(acc[2][1], c2c, u11.x); fma2(acc[2][1], c2d, u11.y);
            fma2(acc[2][2], c2a, u20.x); fma2(acc[2][2], c2b, u20.y);
            fma2(acc[2][2], c2c, u21.x); fma2(acc[2][2], c2d, u21.y);
            fma2(acc[2][3], c2a, u30.x); fma2(acc[2][3], c2b, u30.y);
            fma2(acc[2][3], c2c, u31.x); fma2(acc[2][3], c2d, u31.y);

            fma2(acc[3][0], c3a, u00.x); fma2(acc[3][0], c3b, u00.y);
            fma2(acc[3][0], c3c, u01.x); fma2(acc[3][0], c3d, u01.y);
            fma2(acc[3][1], c3a, u10.x); fma2(acc[3][1], c3b, u10.y);
            fma2(acc[3][1], c3c, u11.x); fma2(acc[3][1], c3d, u11.y);
            fma2(acc[3][2], c3a, u20.x); fma2(acc[3][2], c3b, u20.y);
            fma2(acc[3][2], c3c, u21.x); fma2(acc[3][2], c3d, u21.y);
            fma2(acc[3][3], c3a, u30.x); fma2(acc[3][3], c3b, u30.y);
            fma2(acc[3][3], c3c, u31.x); fma2(acc[3][3], c3d, u31.y);
        }

        const int s_tab = og >> 1;
        const int hoff  = (og & 1) * 4;
        int rows[4] = {row0, row1, row2, row3};
#pragma unroll
        for (int j = 0; j < 4; j++) {
            float v[4];
#pragma unroll
            for (int i = 0; i < 4; i++) {
                float lo, hi; upk2(acc[j][i], lo, hi);
                v[i] = lo + hi;
            }
#pragma unroll
            for (int i = 0; i < 4; i++)
                v[i] += __shfl_xor_sync(0xffffffffu, v[i], 16);
            if (fq == 0 && rows[j] < NN) {
                float4 o4 = make_float4(v[0], v[1], v[2], v[3]);
                *(float4*)&g_scores[s_tab][((size_t)b * NN + rows[j]) * NH + hoff] = o4;
            }
        }
    }
}

// ---------------------------------------------------------------------------
// K3: out[i] = sigmoid(scores_src[head[i]] + scores_trg[tail[i]])
// ---------------------------------------------------------------------------
__global__ void k_gather(const void* __restrict__ head,
                         const void* __restrict__ tail,
                         float* __restrict__ out, int total) {
    int i = blockIdx.x * blockDim.x + threadIdx.x;
    if (i * 4 >= total) return;

    long long h[4], t[4];
    if (g_idx_is64) {
        longlong2 a0 = ((const longlong2*)head)[2 * i];
        longlong2 a1 = ((const longlong2*)head)[2 * i + 1];
        longlong2 b0 = ((const longlong2*)tail)[2 * i];
        longlong2 b1 = ((const longlong2*)tail)[2 * i + 1];
        h[0] = a0.x; h[1] = a0.y; h[2] = a1.x; h[3] = a1.y;
        t[0] = b0.x; t[1] = b0.y; t[2] = b1.x; t[3] = b1.y;
    } else {
        int4 a = ((const int4*)head)[i];
        int4 c = ((const int4*)tail)[i];
        h[0] = a.x; h[1] = a.y; h[2] = a.z; h[3] = a.w;
        t[0] = c.x; t[1] = c.y; t[2] = c.z; t[3] = c.w;
    }

    float x[4];
#pragma unroll
    for (int k = 0; k < 4; k++)
        x[k] = g_scores[0][h[k]] + g_scores[1][t[k]];

    float4 r;
    r.x = 1.f / (1.f + __expf(-x[0]));
    r.y = 1.f / (1.f + __expf(-x[1]));
    r.z = 1.f / (1.f + __expf(-x[2]));
    r.w = 1.f / (1.f + __expf(-x[3]));
    ((float4*)out)[i] = r;
}

// ---------------------------------------------------------------------------
extern "C" void kernel_launch(void* const* d_in, const int* in_sizes, int n_in,
                              void* d_out, int out_size) {
    const float* ch   = (const float*)d_in[0];
    const void*  head = d_in[1];
    const void*  tail = d_in[2];
    const float* W    = (const float*)d_in[3];
    const float* src  = (const float*)d_in[4];
    const float* trg  = (const float*)d_in[5];
    float* out = (float*)d_out;

    k_prep<<<BSZ * 2 * NH * 4, 256>>>(W, src, trg, (const unsigned int*)head);

    dim3 g2(NBX, BSZ);
    k_scores<<<g2, 256>>>(ch);

    int total = BSZ * EE;                       // 1,280,000 (multiple of 4)
    int groups = total / 4;
    k_gather<<<(groups + 255) / 256, 256>>>(head, tail, out, total);
}